// round 1
// baseline (speedup 1.0000x reference)
#include <cuda_runtime.h>
#include <math.h>

// Problem dims (fixed)
#define BATCH 4
#define SEQ   8192
#define DIM   512
#define HEADS 8
#define DHEAD 64
#define MROWS (BATCH*SEQ)

// scan chunking
#define CHUNK  128
#define NCHUNK (SEQ/CHUNK)

// device scratch (allocation-free rule -> __device__ globals)
__device__ float g_xp[(size_t)MROWS*DIM];
__device__ float g_y [(size_t)MROWS*DIM];
__device__ float g_e  [(size_t)BATCH*NCHUNK*DIM];
__device__ float g_cin[(size_t)BATCH*NCHUNK*DIM];
__device__ float g_alpha[HEADS];

// ---------------------------------------------------------------------------
// alpha = sigmoid(alpha_param)
// ---------------------------------------------------------------------------
__global__ void alpha_kernel(const float* __restrict__ ap) {
    int h = threadIdx.x;
    if (h < HEADS) g_alpha[h] = 1.0f / (1.0f + expf(-ap[h]));
}

// ---------------------------------------------------------------------------
// fp32 GEMM: C[m,n] = sum_k A[m,k] * W[n,k] + bias[n]
// A: [MROWS, DIM] row-major, W: [DIM, DIM] row-major (both K-contiguous)
// 128x128 block tile, BK=16, 256 threads, 8x8 per-thread tile.
// ---------------------------------------------------------------------------
#define BM 128
#define BN 128
#define BK 16

__device__ __forceinline__ void gemm_body(const float* __restrict__ A,
                                          const float* __restrict__ Bw,
                                          const float* __restrict__ bias,
                                          float* __restrict__ C) {
    __shared__ float As[BK][BM + 4];
    __shared__ float Bs[BK][BN + 4];

    const int tid = threadIdx.x;
    const int tx = tid & 15;     // 0..15 -> n
    const int ty = tid >> 4;     // 0..15 -> m
    const int m0 = blockIdx.y * BM;
    const int n0 = blockIdx.x * BN;

    const float* Ab = A  + (size_t)m0 * DIM;
    const float* Bb = Bw + (size_t)n0 * DIM;

    float acc[8][8];
#pragma unroll
    for (int i = 0; i < 8; i++)
#pragma unroll
        for (int j = 0; j < 8; j++) acc[i][j] = 0.0f;

    const int lrow = tid >> 2;        // 0..63
    const int lk   = (tid & 3) * 4;   // 0,4,8,12

    for (int k0 = 0; k0 < DIM; k0 += BK) {
#pragma unroll
        for (int r = 0; r < 2; r++) {
            int row = lrow + r * 64;
            float4 va = *(const float4*)(Ab + (size_t)row * DIM + k0 + lk);
            As[lk + 0][row] = va.x;
            As[lk + 1][row] = va.y;
            As[lk + 2][row] = va.z;
            As[lk + 3][row] = va.w;
            float4 vb = *(const float4*)(Bb + (size_t)row * DIM + k0 + lk);
            Bs[lk + 0][row] = vb.x;
            Bs[lk + 1][row] = vb.y;
            Bs[lk + 2][row] = vb.z;
            Bs[lk + 3][row] = vb.w;
        }
        __syncthreads();
#pragma unroll
        for (int k = 0; k < BK; k++) {
            float ar[8], br[8];
            *(float4*)&ar[0] = *(const float4*)&As[k][ty * 8];
            *(float4*)&ar[4] = *(const float4*)&As[k][ty * 8 + 4];
            *(float4*)&br[0] = *(const float4*)&Bs[k][tx * 8];
            *(float4*)&br[4] = *(const float4*)&Bs[k][tx * 8 + 4];
#pragma unroll
            for (int i = 0; i < 8; i++)
#pragma unroll
                for (int j = 0; j < 8; j++)
                    acc[i][j] = fmaf(ar[i], br[j], acc[i][j]);
        }
        __syncthreads();
    }

    float bv[8];
#pragma unroll
    for (int j = 0; j < 8; j++) bv[j] = bias[n0 + tx * 8 + j];
#pragma unroll
    for (int i = 0; i < 8; i++) {
        float* Crow = C + (size_t)(m0 + ty * 8 + i) * DIM + n0 + tx * 8;
        float4 o0 = make_float4(acc[i][0] + bv[0], acc[i][1] + bv[1],
                                acc[i][2] + bv[2], acc[i][3] + bv[3]);
        float4 o1 = make_float4(acc[i][4] + bv[4], acc[i][5] + bv[5],
                                acc[i][6] + bv[6], acc[i][7] + bv[7]);
        *(float4*)(Crow)     = o0;
        *(float4*)(Crow + 4) = o1;
    }
}

__global__ void __launch_bounds__(256)
gemm1_kernel(const float* __restrict__ x, const float* __restrict__ W,
             const float* __restrict__ bias) {
    gemm_body(x, W, bias, g_xp);
}

__global__ void __launch_bounds__(256)
gemm2_kernel(const float* __restrict__ W, const float* __restrict__ bias,
             float* __restrict__ out) {
    gemm_body(g_y, W, bias, out);
}

// ---------------------------------------------------------------------------
// Chunked linear scan: y[t] = a*y[t-1] + alpha*(xp[t]-xp[t-1]),
// y[-1] = xp[-1] = init_state (flattened [H*Dh] == channel index d).
// ---------------------------------------------------------------------------
__global__ void chunk_end_kernel(const float* __restrict__ init_state) {
    int d = threadIdx.x;
    int c = blockIdx.x, b = blockIdx.y;
    float alpha = g_alpha[d >> 6];
    float a = 1.0f - alpha;
    int t0 = c * CHUNK;
    const float* base = g_xp + ((size_t)b * SEQ + t0) * DIM + d;
    float prev = (t0 == 0) ? init_state[d] : *(base - DIM);
    float l = 0.0f;
#pragma unroll 4
    for (int t = 0; t < CHUNK; t++) {
        float cur = base[(size_t)t * DIM];
        l = a * l + alpha * (cur - prev);
        prev = cur;
    }
    g_e[((size_t)b * NCHUNK + c) * DIM + d] = l;
}

__global__ void carry_kernel(const float* __restrict__ init_state) {
    int d = threadIdx.x;
    int b = blockIdx.x;
    float a = 1.0f - g_alpha[d >> 6];
    float aN = powf(a, (float)CHUNK);
    float carry = init_state[d];
    for (int c = 0; c < NCHUNK; c++) {
        size_t idx = ((size_t)b * NCHUNK + c) * DIM + d;
        g_cin[idx] = carry;
        carry = aN * carry + g_e[idx];
    }
}

__global__ void scan_kernel(const float* __restrict__ init_state) {
    int d = threadIdx.x;
    int c = blockIdx.x, b = blockIdx.y;
    float alpha = g_alpha[d >> 6];
    float a = 1.0f - alpha;
    int t0 = c * CHUNK;
    size_t off = ((size_t)b * SEQ + t0) * DIM + d;
    const float* base = g_xp + off;
    float* yout = g_y + off;
    float prev = (t0 == 0) ? init_state[d] : *(base - DIM);
    float l = g_cin[((size_t)b * NCHUNK + c) * DIM + d];
#pragma unroll 4
    for (int t = 0; t < CHUNK; t++) {
        float cur = base[(size_t)t * DIM];
        l = a * l + alpha * (cur - prev);
        yout[(size_t)t * DIM] = l;
        prev = cur;
    }
}

// ---------------------------------------------------------------------------
// launch
// ---------------------------------------------------------------------------
extern "C" void kernel_launch(void* const* d_in, const int* in_sizes, int n_in,
                              void* d_out, int out_size) {
    const float* x    = (const float*)d_in[0];
    const float* Win  = (const float*)d_in[1];
    const float* bin  = (const float*)d_in[2];
    const float* Wout = (const float*)d_in[3];
    const float* bout = (const float*)d_in[4];
    const float* init = (const float*)d_in[5];
    const float* ap   = (const float*)d_in[6];
    float* out = (float*)d_out;

    alpha_kernel<<<1, 32>>>(ap);

    dim3 ggrid(DIM / BN, MROWS / BM);
    gemm1_kernel<<<ggrid, 256>>>(x, Win, bin);

    chunk_end_kernel<<<dim3(NCHUNK, BATCH), DIM>>>(init);
    carry_kernel<<<BATCH, DIM>>>(init);
    scan_kernel<<<dim3(NCHUNK, BATCH), DIM>>>(init);

    gemm2_kernel<<<ggrid, 256>>>(Wout, bout, out);
}

// round 3
// speedup vs baseline: 2.2984x; 2.2984x over previous
#include <cuda_runtime.h>
#include <cuda_bf16.h>
#include <math.h>
#include <stdint.h>

// Problem dims (fixed)
#define BATCH 4
#define SEQ   8192
#define DIM   512
#define HEADS 8
#define MROWS (BATCH*SEQ)

// scan chunking
#define CHUNK  128
#define NCHUNK (SEQ/CHUNK)

typedef __nv_bfloat16 bf16;

// ---------------------------------------------------------------------------
// device scratch (allocation-free rule -> __device__ globals)
// ---------------------------------------------------------------------------
__device__ float g_xp [(size_t)MROWS*DIM];     // GEMM1 output (fp32)
__device__ bf16  g_ah [(size_t)MROWS*DIM];     // x split hi
__device__ bf16  g_al [(size_t)MROWS*DIM];     // x split lo
__device__ bf16  g_yh [(size_t)MROWS*DIM];     // y split hi
__device__ bf16  g_yl [(size_t)MROWS*DIM];     // y split lo
__device__ bf16  g_w1h[DIM*DIM];
__device__ bf16  g_w1l[DIM*DIM];
__device__ bf16  g_w2h[DIM*DIM];
__device__ bf16  g_w2l[DIM*DIM];
__device__ float g_e  [(size_t)BATCH*NCHUNK*DIM];
__device__ float g_cin[(size_t)BATCH*NCHUNK*DIM];
__device__ float g_alpha[HEADS];

// ---------------------------------------------------------------------------
// helpers
// ---------------------------------------------------------------------------
__device__ __forceinline__ uint32_t s2u(const void* p) {
    uint32_t a;
    asm("{ .reg .u64 t; cvta.to.shared.u64 t, %1; cvt.u32.u64 %0, t; }"
        : "=r"(a) : "l"(p));
    return a;
}

__device__ __forceinline__ void ldsm4(uint32_t& r0, uint32_t& r1,
                                      uint32_t& r2, uint32_t& r3,
                                      uint32_t addr) {
    asm volatile("ldmatrix.sync.aligned.m8n8.x4.shared.b16 {%0,%1,%2,%3}, [%4];"
                 : "=r"(r0), "=r"(r1), "=r"(r2), "=r"(r3) : "r"(addr));
}

__device__ __forceinline__ void mma16816(float* c, const uint32_t* a,
                                         const uint32_t* b) {
    asm volatile(
        "mma.sync.aligned.m16n8k16.row.col.f32.bf16.bf16.f32 "
        "{%0,%1,%2,%3}, {%4,%5,%6,%7}, {%8,%9}, {%0,%1,%2,%3};"
        : "+f"(c[0]), "+f"(c[1]), "+f"(c[2]), "+f"(c[3])
        : "r"(a[0]), "r"(a[1]), "r"(a[2]), "r"(a[3]), "r"(b[0]), "r"(b[1]));
}

// ---------------------------------------------------------------------------
// alpha = sigmoid(alpha_param)
// ---------------------------------------------------------------------------
__global__ void alpha_kernel(const float* __restrict__ ap) {
    int h = threadIdx.x;
    if (h < HEADS) g_alpha[h] = 1.0f / (1.0f + expf(-ap[h]));
}

// ---------------------------------------------------------------------------
// fp32 -> bf16 hi/lo split (vectorized by 4)
// ---------------------------------------------------------------------------
__global__ void __launch_bounds__(256)
split_kernel(const float* __restrict__ src, bf16* __restrict__ hi,
             bf16* __restrict__ lo, int n4) {
    int i = blockIdx.x * blockDim.x + threadIdx.x;
    if (i >= n4) return;
    float4 v = ((const float4*)src)[i];
    float f[4] = {v.x, v.y, v.z, v.w};
    __nv_bfloat162 h[2], l[2];
#pragma unroll
    for (int k = 0; k < 2; k++) {
        bf16 h0 = __float2bfloat16(f[2*k]);
        bf16 h1 = __float2bfloat16(f[2*k+1]);
        bf16 l0 = __float2bfloat16(f[2*k]   - __bfloat162float(h0));
        bf16 l1 = __float2bfloat16(f[2*k+1] - __bfloat162float(h1));
        h[k].x = h0; h[k].y = h1;
        l[k].x = l0; l[k].y = l1;
    }
    ((__nv_bfloat162*)(hi + 4*(size_t)i))[0] = h[0];
    ((__nv_bfloat162*)(hi + 4*(size_t)i))[1] = h[1];
    ((__nv_bfloat162*)(lo + 4*(size_t)i))[0] = l[0];
    ((__nv_bfloat162*)(lo + 4*(size_t)i))[1] = l[1];
}

// ---------------------------------------------------------------------------
// bf16-split HMMA GEMM: C[m,n] = sum_k A[m,k]*B[n,k] + bias[n]
//   A = Ah+Al [MROWS,DIM], B = Bh+Bl [DIM,DIM]; C fp32.
//   CTA 128x128, BK=64, 256 thr (8 warps, 2x4), warp tile 64x32.
//   cp.async double buffer; SW128 xor swizzle; ldmatrix.x4; mma.m16n8k16.
// ---------------------------------------------------------------------------
#define BM 128
#define BN 128
#define BK 64
#define KITERS (DIM/BK)     // 8

#define AH_OFF 0
#define AL_OFF 16384
#define BH_OFF 32768
#define BL_OFF 49152
#define STAGE_BYTES 65536
#define SMEM_TOTAL (2*STAGE_BYTES)

// swizzled byte offset inside a [128 rows x 128B] tile
#define TSWZ(row, c16) ((uint32_t)(row) * 128u + 16u * ((uint32_t)(c16) ^ ((uint32_t)(row) & 7u)))

__device__ __forceinline__ void load_stage(uint32_t sbase,
                                           const bf16* __restrict__ Ah,
                                           const bf16* __restrict__ Al,
                                           const bf16* __restrict__ Bh,
                                           const bf16* __restrict__ Bl,
                                           int m0, int n0, int k0, int tid) {
    // 4 matrices x 128 rows x 8 chunks(16B) = 4096 cp.async of 16B
#pragma unroll
    for (int q = 0; q < 16; q++) {
        int i = tid + q * 256;
        int mat = i >> 10;            // 0 Ah, 1 Al, 2 Bh, 3 Bl
        int j = i & 1023;
        int row = j >> 3;
        int c = j & 7;
        const bf16* src;
        uint32_t moff;
        if (mat == 0)      { src = Ah + (size_t)(m0 + row) * DIM; moff = AH_OFF; }
        else if (mat == 1) { src = Al + (size_t)(m0 + row) * DIM; moff = AL_OFF; }
        else if (mat == 2) { src = Bh + (size_t)(n0 + row) * DIM; moff = BH_OFF; }
        else               { src = Bl + (size_t)(n0 + row) * DIM; moff = BL_OFF; }
        src += k0 + c * 8;
        uint32_t dst = sbase + moff + TSWZ(row, c);
        asm volatile("cp.async.cg.shared.global [%0], [%1], 16;"
                     :: "r"(dst), "l"(src));
    }
}

__global__ void __launch_bounds__(256, 1)
gemm_mma(const bf16* __restrict__ Ah, const bf16* __restrict__ Al,
         const bf16* __restrict__ Bh, const bf16* __restrict__ Bl,
         const float* __restrict__ bias, float* __restrict__ C) {
    extern __shared__ char smem[];
    uint32_t sb = s2u(smem);

    const int tid  = threadIdx.x;
    const int wid  = tid >> 5;
    const int lane = tid & 31;
    const int wm   = wid >> 2;           // 0..1 -> 64 rows each
    const int wn   = wid & 3;            // 0..3 -> 32 cols each
    const int m0   = blockIdx.y * BM;
    const int n0   = blockIdx.x * BN;

    float acc[4][4][4];
#pragma unroll
    for (int i = 0; i < 4; i++)
#pragma unroll
        for (int j = 0; j < 4; j++)
#pragma unroll
            for (int r = 0; r < 4; r++) acc[i][j][r] = 0.0f;

    // lane-invariant pieces of ldmatrix addresses
    const int arow = wm * 64 + (lane & 15);           // + mt*16
    const int achk = lane >> 4;                       // + 2*ks
    const int brow = wn * 32 + (lane & 7) + ((lane >> 4) << 3);  // + nt2*16
    const int bchk = (lane >> 3) & 1;                 // + 2*ks
    const uint32_t sxor = (uint32_t)(lane & 7);

    // prologue
    load_stage(sb, Ah, Al, Bh, Bl, m0, n0, 0, tid);
    asm volatile("cp.async.commit_group;" ::: "memory");

    for (int it = 0; it < KITERS; it++) {
        if (it + 1 < KITERS) {
            load_stage(sb + ((it + 1) & 1) * STAGE_BYTES,
                       Ah, Al, Bh, Bl, m0, n0, (it + 1) * BK, tid);
            asm volatile("cp.async.commit_group;" ::: "memory");
            asm volatile("cp.async.wait_group 1;" ::: "memory");
        } else {
            asm volatile("cp.async.wait_group 0;" ::: "memory");
        }
        __syncthreads();

        uint32_t st = sb + (it & 1) * STAGE_BYTES;
#pragma unroll
        for (int ks = 0; ks < BK / 16; ks++) {
            uint32_t ah[4][4], al[4][4];
#pragma unroll
            for (int mt = 0; mt < 4; mt++) {
                int row = arow + mt * 16;
                uint32_t co = (uint32_t)(2 * ks + achk) ^ sxor;
                uint32_t off = (uint32_t)row * 128u + co * 16u;
                ldsm4(ah[mt][0], ah[mt][1], ah[mt][2], ah[mt][3],
                      st + AH_OFF + off);
                ldsm4(al[mt][0], al[mt][1], al[mt][2], al[mt][3],
                      st + AL_OFF + off);
            }
            uint32_t bh[4][2], bl[4][2];
#pragma unroll
            for (int nt2 = 0; nt2 < 2; nt2++) {
                int row = brow + nt2 * 16;
                uint32_t co = (uint32_t)(2 * ks + bchk) ^ sxor;
                uint32_t off = (uint32_t)row * 128u + co * 16u;
                uint32_t r0, r1, r2, r3;
                ldsm4(r0, r1, r2, r3, st + BH_OFF + off);
                bh[nt2*2][0] = r0; bh[nt2*2][1] = r1;
                bh[nt2*2+1][0] = r2; bh[nt2*2+1][1] = r3;
                ldsm4(r0, r1, r2, r3, st + BL_OFF + off);
                bl[nt2*2][0] = r0; bl[nt2*2][1] = r1;
                bl[nt2*2+1][0] = r2; bl[nt2*2+1][1] = r3;
            }
#pragma unroll
            for (int mt = 0; mt < 4; mt++)
#pragma unroll
                for (int nt = 0; nt < 4; nt++) {
                    mma16816(acc[mt][nt], ah[mt], bh[nt]);
                    mma16816(acc[mt][nt], al[mt], bh[nt]);
                    mma16816(acc[mt][nt], ah[mt], bl[nt]);
                }
        }
        __syncthreads();
    }

    // epilogue: acc -> C (+bias). c0,c1: row lane/4, cols 2(l%4)+{0,1}; c2,c3 row+8
    const int erow = m0 + wm * 64 + (lane >> 2);
    const int ecol = n0 + wn * 32 + 2 * (lane & 3);
#pragma unroll
    for (int nt = 0; nt < 4; nt++) {
        int col = ecol + nt * 8;
        float b0 = bias[col], b1 = bias[col + 1];
#pragma unroll
        for (int mt = 0; mt < 4; mt++) {
            int row = erow + mt * 16;
            float2 v0 = make_float2(acc[mt][nt][0] + b0, acc[mt][nt][1] + b1);
            float2 v1 = make_float2(acc[mt][nt][2] + b0, acc[mt][nt][3] + b1);
            *(float2*)(C + (size_t)row * DIM + col)       = v0;
            *(float2*)(C + (size_t)(row + 8) * DIM + col) = v1;
        }
    }
}

// ---------------------------------------------------------------------------
// Chunked linear scan: y[t] = a*y[t-1] + alpha*(xp[t]-xp[t-1]),
// y[-1] = xp[-1] = init_state (channel index d = h*64 + dh)
// ---------------------------------------------------------------------------
__global__ void chunk_end_kernel(const float* __restrict__ init_state) {
    int d = threadIdx.x;
    int c = blockIdx.x, b = blockIdx.y;
    float alpha = g_alpha[d >> 6];
    float a = 1.0f - alpha;
    int t0 = c * CHUNK;
    const float* base = g_xp + ((size_t)b * SEQ + t0) * DIM + d;
    float prev = (t0 == 0) ? init_state[d] : *(base - DIM);
    float l = 0.0f;
#pragma unroll 4
    for (int t = 0; t < CHUNK; t++) {
        float cur = base[(size_t)t * DIM];
        l = a * l + alpha * (cur - prev);
        prev = cur;
    }
    g_e[((size_t)b * NCHUNK + c) * DIM + d] = l;
}

__global__ void __launch_bounds__(512)
carry_kernel(const float* __restrict__ init_state) {
    int d = threadIdx.x;
    int b = blockIdx.x;
    float a = 1.0f - g_alpha[d >> 6];
    float aN = powf(a, (float)CHUNK);
    float e[NCHUNK];
#pragma unroll
    for (int c = 0; c < NCHUNK; c++)
        e[c] = g_e[((size_t)b * NCHUNK + c) * DIM + d];
    float carry = init_state[d];
#pragma unroll
    for (int c = 0; c < NCHUNK; c++) {
        g_cin[((size_t)b * NCHUNK + c) * DIM + d] = carry;
        carry = fmaf(aN, carry, e[c]);
    }
}

__global__ void scan_kernel(const float* __restrict__ init_state) {
    int d = threadIdx.x;
    int c = blockIdx.x, b = blockIdx.y;
    float alpha = g_alpha[d >> 6];
    float a = 1.0f - alpha;
    int t0 = c * CHUNK;
    size_t off = ((size_t)b * SEQ + t0) * DIM + d;
    const float* base = g_xp + off;
    bf16* yh = g_yh + off;
    bf16* yl = g_yl + off;
    float prev = (t0 == 0) ? init_state[d] : *(base - DIM);
    float l = g_cin[((size_t)b * NCHUNK + c) * DIM + d];
#pragma unroll 4
    for (int t = 0; t < CHUNK; t++) {
        float cur = base[(size_t)t * DIM];
        l = a * l + alpha * (cur - prev);
        prev = cur;
        bf16 h = __float2bfloat16(l);
        yh[(size_t)t * DIM] = h;
        yl[(size_t)t * DIM] = __float2bfloat16(l - __bfloat162float(h));
    }
}

// ---------------------------------------------------------------------------
// launch
// ---------------------------------------------------------------------------
extern "C" void kernel_launch(void* const* d_in, const int* in_sizes, int n_in,
                              void* d_out, int out_size) {
    const float* x    = (const float*)d_in[0];
    const float* Win  = (const float*)d_in[1];
    const float* bin  = (const float*)d_in[2];
    const float* Wout = (const float*)d_in[3];
    const float* bout = (const float*)d_in[4];
    const float* init = (const float*)d_in[5];
    const float* ap   = (const float*)d_in[6];
    float* out = (float*)d_out;

    cudaFuncSetAttribute(gemm_mma, cudaFuncAttributeMaxDynamicSharedMemorySize,
                         SMEM_TOTAL);

    alpha_kernel<<<1, 32>>>(ap);

    bf16 *ah, *al, *w1h, *w1l, *w2h, *w2l, *yh, *yl;
    float *xp;
    cudaGetSymbolAddress((void**)&ah,  g_ah);
    cudaGetSymbolAddress((void**)&al,  g_al);
    cudaGetSymbolAddress((void**)&w1h, g_w1h);
    cudaGetSymbolAddress((void**)&w1l, g_w1l);
    cudaGetSymbolAddress((void**)&w2h, g_w2h);
    cudaGetSymbolAddress((void**)&w2l, g_w2l);
    cudaGetSymbolAddress((void**)&yh,  g_yh);
    cudaGetSymbolAddress((void**)&yl,  g_yl);
    cudaGetSymbolAddress((void**)&xp,  g_xp);

    int n4x = (MROWS * DIM) / 4;
    split_kernel<<<(n4x + 255) / 256, 256>>>(x, ah, al, n4x);
    int n4w = (DIM * DIM) / 4;
    split_kernel<<<(n4w + 255) / 256, 256>>>(Win,  w1h, w1l, n4w);
    split_kernel<<<(n4w + 255) / 256, 256>>>(Wout, w2h, w2l, n4w);

    dim3 ggrid(DIM / BN, MROWS / BM);
    gemm_mma<<<ggrid, 256, SMEM_TOTAL>>>(ah, al, w1h, w1l, bin, xp);

    chunk_end_kernel<<<dim3(NCHUNK, BATCH), DIM>>>(init);
    carry_kernel<<<BATCH, DIM>>>(init);
    scan_kernel<<<dim3(NCHUNK, BATCH), DIM>>>(init);

    gemm_mma<<<ggrid, 256, SMEM_TOTAL>>>(yh, yl, w2h, w2l, bout, out);
}